// round 6
// baseline (speedup 1.0000x reference)
#include <cuda_runtime.h>
#include <cuda_bf16.h>
#include <math.h>

// Problem constants (shapes fixed by the reference)
#define MAXN 50000
#define FDIM 128
#define GMAX 64
#define CDIM 2

// ---------------------------------------------------------------------------
// Scratch (static __device__ — no allocation allowed)
// ---------------------------------------------------------------------------
__device__ float g_deg [MAXN];
__device__ float g_dinv[MAXN];
__device__ float g_H   [MAXN * FDIM];   // pre-aggregation features (h = A @ W)
__device__ float g_O   [MAXN * FDIM];   // post-aggregation output (init self-loop+bias)
__device__ float g_pool[GMAX * FDIM];

// ---------------------------------------------------------------------------
// Helpers
// ---------------------------------------------------------------------------
__device__ __forceinline__ void red_add_v4(float* addr, float4 v) {
    asm volatile("red.global.add.v4.f32 [%0], {%1,%2,%3,%4};"
                 :: "l"(addr), "f"(v.x), "f"(v.y), "f"(v.z), "f"(v.w) : "memory");
}

__device__ __forceinline__ void atomicMaxFloat(float* a, float v) {
    if (v >= 0.f) atomicMax((int*)a, __float_as_int(v));
    else          atomicMin((unsigned int*)a, __float_as_uint(v));
}

// ---------------------------------------------------------------------------
// K1: init deg (=1 for self loop) and pool buffer (=-FLT_MAX)
// ---------------------------------------------------------------------------
__global__ void init_kernel(int n, int gtot) {
    int i = blockIdx.x * blockDim.x + threadIdx.x;
    if (i < n) g_deg[i] = 1.0f;
    if (i < gtot) g_pool[i] = -3.402823466e38f;
}

// K2: accumulate in-degree over edges
__global__ void deg_kernel(const int* __restrict__ dst, int E) {
    int e = blockIdx.x * blockDim.x + threadIdx.x;
    if (e < E) atomicAdd(&g_deg[dst[e]], 1.0f);
}

// K3: dinv = rsqrt(deg)   (deg >= 1 always, self-loops)
__global__ void dinv_kernel(int n) {
    int i = blockIdx.x * blockDim.x + threadIdx.x;
    if (i < n) g_dinv[i] = rsqrtf(g_deg[i]);
}

// ---------------------------------------------------------------------------
// K4/K6: SGEMM  H = act(A) @ W  [M x 128] x [128 x 128]
//        fused epilogue: O = H * dinv[row]^2 + bias[col]   (self-loop + bias)
// 128x128 block tile, BK=32, 256 threads, 8x8 micro-tile per thread.
// ---------------------------------------------------------------------------
template<bool RELU_A>
__global__ __launch_bounds__(256, 2)
void gemm_gcn(const float* __restrict__ A, const float* __restrict__ W,
              const float* __restrict__ bias,
              float* __restrict__ Hout, float* __restrict__ Oout, int M)
{
    const int BK = 32;
    __shared__ float As[128][36];          // padded: 36*4B rows, 16B-aligned cols
    __shared__ float Bs[BK][128];

    int block_row = blockIdx.x * 128;
    int tid = threadIdx.x;
    int ty = tid >> 4;       // 0..15
    int tx = tid & 15;       // 0..15

    float acc[8][8];
#pragma unroll
    for (int i = 0; i < 8; i++)
#pragma unroll
        for (int j = 0; j < 8; j++) acc[i][j] = 0.f;

    for (int k0 = 0; k0 < 128; k0 += BK) {
        // load A tile (128 x 32), 4 float4 per thread
#pragma unroll
        for (int i = 0; i < 4; i++) {
            int s  = tid + i * 256;      // 0..1023
            int m  = s >> 3;             // 0..127
            int kk = (s & 7) * 4;        // 0..28
            int gr = block_row + m;
            float4 v = make_float4(0.f, 0.f, 0.f, 0.f);
            if (gr < M) v = *(const float4*)(A + (size_t)gr * FDIM + k0 + kk);
            if (RELU_A) {
                v.x = fmaxf(v.x, 0.f); v.y = fmaxf(v.y, 0.f);
                v.z = fmaxf(v.z, 0.f); v.w = fmaxf(v.w, 0.f);
            }
            *(float4*)&As[m][kk] = v;
        }
        // load B tile (32 x 128), 4 float4 per thread
#pragma unroll
        for (int i = 0; i < 4; i++) {
            int s  = tid + i * 256;
            int kk = s >> 5;             // 0..31
            int n4 = (s & 31) * 4;       // 0..124
            *(float4*)&Bs[kk][n4] = *(const float4*)(W + (size_t)(k0 + kk) * FDIM + n4);
        }
        __syncthreads();

#pragma unroll
        for (int k = 0; k < BK; k++) {
            float a[8], b[8];
#pragma unroll
            for (int i = 0; i < 8; i++) a[i] = As[ty * 8 + i][k];
#pragma unroll
            for (int j = 0; j < 8; j++) b[j] = Bs[k][tx * 8 + j];
#pragma unroll
            for (int i = 0; i < 8; i++)
#pragma unroll
                for (int j = 0; j < 8; j++) acc[i][j] += a[i] * b[j];
        }
        __syncthreads();
    }

    // epilogue: H = acc ; O = acc * dinv^2 + bias
#pragma unroll
    for (int i = 0; i < 8; i++) {
        int gr = block_row + ty * 8 + i;
        if (gr >= M) break;
        float dv = g_dinv[gr];
        float sc = dv * dv;
#pragma unroll
        for (int j = 0; j < 8; j += 4) {
            int col = tx * 8 + j;
            float4 h = make_float4(acc[i][j], acc[i][j+1], acc[i][j+2], acc[i][j+3]);
            *(float4*)(Hout + (size_t)gr * FDIM + col) = h;
            float4 bv = *(const float4*)(bias + col);
            float4 o = make_float4(h.x * sc + bv.x, h.y * sc + bv.y,
                                   h.z * sc + bv.z, h.w * sc + bv.w);
            *(float4*)(Oout + (size_t)gr * FDIM + col) = o;
        }
    }
}

// ---------------------------------------------------------------------------
// K5/K7: edge aggregation. One warp per edge:
//   O[dst] += dinv[src]*dinv[dst] * H[src]   via red.global.add.v4.f32
// ---------------------------------------------------------------------------
__global__ __launch_bounds__(256)
void agg_kernel(const int* __restrict__ src, const int* __restrict__ dst, int E)
{
    int warp = (blockIdx.x * blockDim.x + threadIdx.x) >> 5;
    if (warp >= E) return;
    int lane = threadIdx.x & 31;
    int s = __ldg(&src[warp]);
    int d = __ldg(&dst[warp]);
    float nm = g_dinv[s] * g_dinv[d];
    float4 v = *(const float4*)(g_H + (size_t)s * FDIM + lane * 4);
    v.x *= nm; v.y *= nm; v.z *= nm; v.w *= nm;
    red_add_v4(g_O + (size_t)d * FDIM + lane * 4, v);
}

// ---------------------------------------------------------------------------
// K8: segment max pool over sorted batch ids. Block = 128 threads (one per col),
// processes a contiguous node range with a running max, flushing on segment change.
// ---------------------------------------------------------------------------
#define POOL_NODES 256
__global__ void pool_kernel(const int* __restrict__ batch, int M)
{
    int j  = threadIdx.x;
    int n0 = blockIdx.x * POOL_NODES;
    int n1 = min(n0 + POOL_NODES, M);
    if (n0 >= M) return;
    int cur = __ldg(&batch[n0]);
    float m = -3.402823466e38f;
    for (int i = n0; i < n1; i++) {
        int b = __ldg(&batch[i]);
        if (b != cur) {
            atomicMaxFloat(&g_pool[cur * FDIM + j], m);
            cur = b;
            m = -3.402823466e38f;
        }
        m = fmaxf(m, g_O[(size_t)i * FDIM + j]);
    }
    atomicMaxFloat(&g_pool[cur * FDIM + j], m);
}

// ---------------------------------------------------------------------------
// K9: MLP head, one block per graph (128 threads)
//   g1 = relu(g@Wl1+bl1); g2 = relu(g1@Wl2+bl2); out = softmax(g2@Wo+bo)
// ---------------------------------------------------------------------------
__global__ void mlp_kernel(const float* __restrict__ Wl1, const float* __restrict__ bl1,
                           const float* __restrict__ Wl2, const float* __restrict__ bl2,
                           const float* __restrict__ Wo,  const float* __restrict__ bo,
                           float* __restrict__ out)
{
    __shared__ float gv[128], t1[128], t2[128], logits[CDIM];
    int g = blockIdx.x, j = threadIdx.x;

    gv[j] = g_pool[g * FDIM + j];
    __syncthreads();

    float acc = bl1[j];
#pragma unroll 8
    for (int k = 0; k < 128; k++) acc += gv[k] * Wl1[k * 128 + j];
    t1[j] = fmaxf(acc, 0.f);
    __syncthreads();

    acc = bl2[j];
#pragma unroll 8
    for (int k = 0; k < 128; k++) acc += t1[k] * Wl2[k * 128 + j];
    t2[j] = fmaxf(acc, 0.f);
    __syncthreads();

    if (j < CDIM) {
        float l = bo[j];
#pragma unroll 8
        for (int k = 0; k < 128; k++) l += t2[k] * Wo[k * CDIM + j];
        logits[j] = l;
    }
    __syncthreads();

    if (j < CDIM) {
        float m = fmaxf(logits[0], logits[1]);
        float e = expf(logits[j] - m);
        float s = expf(logits[0] - m) + expf(logits[1] - m);
        out[g * CDIM + j] = e / s;
    }
}

// ---------------------------------------------------------------------------
// Launch: inputs in metadata order:
// 0:x 1:edge_index 2:batch 3:W1 4:b1 5:W2 6:b2 7:Wl1 8:bl1 9:Wl2 10:bl2 11:Wo 12:bo
// ---------------------------------------------------------------------------
extern "C" void kernel_launch(void* const* d_in, const int* in_sizes, int n_in,
                              void* d_out, int out_size)
{
    const float* x    = (const float*)d_in[0];
    const int*   ei   = (const int*)  d_in[1];
    const int*   batch= (const int*)  d_in[2];
    const float* W1   = (const float*)d_in[3];
    const float* b1   = (const float*)d_in[4];
    const float* W2   = (const float*)d_in[5];
    const float* b2   = (const float*)d_in[6];
    const float* Wl1  = (const float*)d_in[7];
    const float* bl1  = (const float*)d_in[8];
    const float* Wl2  = (const float*)d_in[9];
    const float* bl2  = (const float*)d_in[10];
    const float* Wo   = (const float*)d_in[11];
    const float* bo   = (const float*)d_in[12];
    float* out = (float*)d_out;

    int N = in_sizes[0] / FDIM;        // 50000
    int E = in_sizes[1] / 2;           // 600000
    int G = out_size / CDIM;           // 64
    const int* src = ei;               // edge_index[0]
    const int* dst = ei + E;           // edge_index[1]

    float *Hp, *Op;
    cudaGetSymbolAddress((void**)&Hp, g_H);
    cudaGetSymbolAddress((void**)&Op, g_O);

    int initN = (N > G * FDIM) ? N : G * FDIM;
    init_kernel<<<(initN + 255) / 256, 256>>>(N, G * FDIM);
    deg_kernel<<<(E + 255) / 256, 256>>>(dst, E);
    dinv_kernel<<<(N + 255) / 256, 256>>>(N);

    int gemm_blocks = (N + 127) / 128;
    // layer 1: H = x@W1 ; O = H*dinv^2 + b1
    gemm_gcn<false><<<gemm_blocks, 256>>>(x, W1, b1, Hp, Op, N);
    {
        long long warps = E;
        int blocks = (int)((warps * 32 + 255) / 256);
        agg_kernel<<<blocks, 256>>>(src, dst, E);
    }
    // layer 2: H = relu(O)@W2 ; O = H*dinv^2 + b2   (O aliasing is block-local safe)
    gemm_gcn<true><<<gemm_blocks, 256>>>(Op, W2, b2, Hp, Op, N);
    {
        long long warps = E;
        int blocks = (int)((warps * 32 + 255) / 256);
        agg_kernel<<<blocks, 256>>>(src, dst, E);
    }
    pool_kernel<<<(N + POOL_NODES - 1) / POOL_NODES, 128>>>(batch, N);
    mlp_kernel<<<G, 128>>>(Wl1, bl1, Wl2, bl2, Wo, bo, out);
}